// round 8
// baseline (speedup 1.0000x reference)
#include <cuda_runtime.h>
#include <cuda_bf16.h>
#include <cstdint>
#include <math.h>

#define BDIM   4096
#define INDIM  256
#define OUTDIM 256
#define NC     8
#define KDIM   (INDIM * NC)      // 2048
#define KSPLIT 2
#define KHALF  (KDIM / KSPLIT)   // 1024

// ---------------- scratch (static device globals; no allocations) ----------
// B stored [i][o][c]  (same layout as coefs => coalesced build)
__device__ __nv_bfloat16 g_Bh[(size_t)INDIM * OUTDIM * NC]; // 1 MB
__device__ float g_part[(size_t)KSPLIT * BDIM * OUTDIM];    // 8 MB partials
__device__ float g_rvp[KSPLIT * BDIM];                      // rv partials
__device__ int   g_cnt[(BDIM / 64) * (OUTDIM / 64)];        // tile arrival counters (zero-init, self-resetting)

// ---------------------------------------------------------------------------
// 1) B[i][o][c] = bf16( spline_scale[i,o] * coefs[i,o,c] )  — pure elementwise
// ---------------------------------------------------------------------------
__global__ __launch_bounds__(256) void build_W_kernel(
    const float* __restrict__ coefs, const float* __restrict__ spline_scale) {
    int idx4 = blockIdx.x * 256 + threadIdx.x;     // float4 group id
    float ss = spline_scale[idx4 >> 1];            // (i,o) = idx4/2
    float4 v = ((const float4*)coefs)[idx4];
    __nv_bfloat162 lo = __floats2bfloat162_rn(ss * v.x, ss * v.y);
    __nv_bfloat162 hi = __floats2bfloat162_rn(ss * v.z, ss * v.w);
    uint2 w;
    w.x = *(uint32_t*)&lo;
    w.y = *(uint32_t*)&hi;
    ((uint2*)g_Bh)[idx4] = w;
}

// ---------------------------------------------------------------------------
// 2) fused GEMM, single-pass bf16, split-K=2, fused combine epilogue
//    CTA 64x64, BK=64, 128 threads (4 warps, warp tile 32x32)
// ---------------------------------------------------------------------------
#define BM 64
#define BN 64
#define BK 64
#define NTS (KHALF / BK)        // 16 k-chunks per split

#define ROWB 144                // 128B data + 16B pad
#define TILE_B (64 * ROWB)      // 9216 per tile
// stage layout: A @0, B @TILE_B
#define STAGE_B (2 * TILE_B)    // 18432
#define GEMM_SMEM (2 * STAGE_B) // 36864

__device__ __forceinline__ uint32_t smem_u32(const void* p) {
    uint32_t a;
    asm("{ .reg .u64 t; cvta.to.shared.u64 t, %1; cvt.u32.u64 %0, t; }"
        : "=r"(a) : "l"(p));
    return a;
}
__device__ __forceinline__ void cp16(uint32_t s, const void* g) {
    asm volatile("cp.async.cg.shared.global [%0], [%1], 16;" :: "r"(s), "l"(g));
}
__device__ __forceinline__ void ldsm_x4(uint32_t* r, uint32_t addr) {
    asm volatile("ldmatrix.sync.aligned.m8n8.x4.shared.b16 {%0,%1,%2,%3}, [%4];"
                 : "=r"(r[0]), "=r"(r[1]), "=r"(r[2]), "=r"(r[3]) : "r"(addr));
}
__device__ __forceinline__ void mma_bf16(float* d, const uint32_t* a, const uint32_t* b) {
    asm volatile(
        "mma.sync.aligned.m16n8k16.row.col.f32.bf16.bf16.f32 "
        "{%0,%1,%2,%3}, {%4,%5,%6,%7}, {%8,%9}, {%0,%1,%2,%3};"
        : "+f"(d[0]), "+f"(d[1]), "+f"(d[2]), "+f"(d[3])
        : "r"(a[0]), "r"(a[1]), "r"(a[2]), "r"(a[3]), "r"(b[0]), "r"(b[1]));
}

// B prefetch from [i][o][c] layout: chunk (c = i-sub 0..7, r = o-sub 0..63)
__device__ __forceinline__ void prefetch_B(uint32_t sbase, int i0, int n0, int tid) {
#pragma unroll
    for (int p = 0; p < 4; ++p) {
        int idx = p * 128 + tid;           // 0..511
        int c = idx >> 6, r = idx & 63;
        cp16(sbase + TILE_B + r * ROWB + c * 16,
             g_Bh + ((size_t)(i0 + c) * OUTDIM + n0 + r) * NC);
    }
    asm volatile("cp.async.commit_group;" ::: "memory");
}

// A compute: 64 rows x 8 i-values; each thread does 4 (b,i) pairs (R6-proven)
__device__ __forceinline__ void compute_A(
    char* abase, int i, int m0, const float* __restrict__ x,
    const float* __restrict__ resid_scale, float* rv_acc,
    float alpha, const float* r1, const float* r2, int tid) {
    const float rs = resid_scale[i];
#pragma unroll
    for (int p = 0; p < 4; ++p) {
        int b = p * 16 + (tid >> 3);
        float t = tanhf(x[(size_t)(m0 + b) * INDIM + i]);
        rv_acc[p] += rs * t;

        float pr[NC];
        pr[0] = 1.0f;
        pr[1] = (alpha + 1.0f) + (alpha + alpha + 2.0f) * (t - 1.0f) * 0.5f;
#pragma unroll
        for (int n = 2; n < NC; n++)
            pr[n] = r1[n] * t * pr[n - 1] - r2[n] * pr[n - 2];

        uint4 uh;
        uint32_t* ph = (uint32_t*)&uh;
#pragma unroll
        for (int c = 0; c < 4; c++) {
            __nv_bfloat162 t2 = __floats2bfloat162_rn(pr[2 * c], pr[2 * c + 1]);
            ph[c] = *(uint32_t*)&t2;
        }
        *(uint4*)(abase + b * ROWB + (tid & 7) * 16) = uh;
    }
}

__global__ __launch_bounds__(128, 5) void gemm_fused(
    float* __restrict__ out, const float* __restrict__ x,
    const float* __restrict__ resid_scale, const float* __restrict__ aat) {
    extern __shared__ char smem[];
    __shared__ int s_old;
    const int tid  = threadIdx.x;
    const int wid  = tid >> 5;
    const int lane = tid & 31;
    const int m0   = blockIdx.x * BM;
    const int n0   = blockIdx.y * BN;
    const int z    = blockIdx.z;
    const int mbase = (wid & 1) * 32;
    const int nbase = (wid >> 1) * 32;
    const uint32_t sb = smem_u32(smem);

    // recurrence coefficients computed locally
    const float alpha = tanhf(__ldg(aat));
    float r1[NC], r2[NC];
#pragma unroll
    for (int n = 2; n < NC; n++) {
        float c = 2.0f * n + 2.0f * alpha;
        float A = 2.0f * n * (n + 2.0f * alpha) * (c - 2.0f);
        r1[n] = (c - 1.0f) * c * (c - 2.0f) / A;
        r2[n] = 2.0f * (n + alpha - 1.0f) * (n + alpha - 1.0f) * c / A;
    }

    float acc[2][4][4];
#pragma unroll
    for (int i = 0; i < 2; i++)
#pragma unroll
        for (int j = 0; j < 4; j++)
#pragma unroll
            for (int r = 0; r < 4; r++) acc[i][j][r] = 0.0f;
    float rv_acc[4] = {0.f, 0.f, 0.f, 0.f};

    // ldmatrix per-lane address pieces (mapping verified R3-R6)
    const int g  = lane >> 3;
    const int lr = lane & 7;
    const int a_row_off = lr + ((g & 1) ? 8 : 0);
    const int kb_off    = (g >= 2) ? 16 : 0;

    const int ibase = z * (KHALF / NC);   // i-range of this split

    // prologue
    compute_A(smem, ibase + (tid & 7), m0, x, resid_scale, rv_acc,
              alpha, r1, r2, tid);
    prefetch_B(sb, ibase, n0, tid);
    prefetch_B(sb + STAGE_B, ibase + 8, n0, tid);
    asm volatile("cp.async.wait_group 1;" ::: "memory");
    __syncthreads();

    for (int kt = 0; kt < NTS; ++kt) {
        const int s = kt & 1;
        const uint32_t st = sb + s * STAGE_B;

#pragma unroll
        for (int ks = 0; ks < 4; ++ks) {
            uint32_t a[2][4], b[4][2];
#pragma unroll
            for (int mf = 0; mf < 2; ++mf) {
                uint32_t row = mbase + mf * 16 + a_row_off;
                ldsm_x4(a[mf], st + row * ROWB + ks * 32 + kb_off);
            }
#pragma unroll
            for (int np = 0; np < 2; ++np) {
                uint32_t row = nbase + np * 16 + lr + ((g >= 2) ? 8 : 0);
                uint32_t kb2 = ks * 32 + ((g & 1) ? 16 : 0);
                uint32_t r4[4];
                ldsm_x4(r4, st + TILE_B + row * ROWB + kb2);
                b[2 * np][0] = r4[0];     b[2 * np][1] = r4[1];
                b[2 * np + 1][0] = r4[2]; b[2 * np + 1][1] = r4[3];
            }
#pragma unroll
            for (int mf = 0; mf < 2; ++mf)
#pragma unroll
                for (int nf = 0; nf < 4; ++nf)
                    mma_bf16(acc[mf][nf], a[mf], b[nf]);
        }
        __syncthreads();   // all warps done reading stage s

        if (kt + 1 < NTS) {
            compute_A(smem + (s ^ 1) * STAGE_B, ibase + (kt + 1) * 8 + (tid & 7),
                      m0, x, resid_scale, rv_acc, alpha, r1, r2, tid);
            if (kt + 2 < NTS) {
                prefetch_B(st, ibase + (kt + 2) * 8, n0, tid);
                asm volatile("cp.async.wait_group 1;" ::: "memory");
            } else {
                asm volatile("cp.async.wait_group 0;" ::: "memory");
            }
            __syncthreads();
        }
    }

    // rv partial: reduce 8 lanes (same b); all CTAs write (same value per
    // (z,m) across blockIdx.y — benign redundant store, needed pre-fence)
#pragma unroll
    for (int p = 0; p < 4; ++p) {
        float v = rv_acc[p];
        v += __shfl_xor_sync(0xffffffffu, v, 1);
        v += __shfl_xor_sync(0xffffffffu, v, 2);
        v += __shfl_xor_sync(0xffffffffu, v, 4);
        if ((lane & 7) == 0)
            g_rvp[z * BDIM + m0 + p * 16 + (tid >> 3)] = v;
    }

    // write partial tile
    float* dst = g_part + (size_t)z * BDIM * OUTDIM;
    const int l4 = lane >> 2, l2 = (lane & 3) * 2;
#pragma unroll
    for (int mf = 0; mf < 2; ++mf) {
        int m = m0 + mbase + mf * 16 + l4;
#pragma unroll
        for (int nf = 0; nf < 4; ++nf) {
            int n = n0 + nbase + nf * 8 + l2;
            *(float2*)&dst[(size_t)m * OUTDIM + n] =
                make_float2(acc[mf][nf][0], acc[mf][nf][1]);
            *(float2*)&dst[(size_t)(m + 8) * OUTDIM + n] =
                make_float2(acc[mf][nf][2], acc[mf][nf][3]);
        }
    }

    // ---- fused combine: second arriver per (mb,nb) tile finishes the job ----
    __threadfence();
    if (tid == 0)
        s_old = atomicAdd(&g_cnt[blockIdx.x * (OUTDIM / BN) + blockIdx.y], 1);
    __syncthreads();

    if (s_old == 1) {
        const float* src = g_part + (size_t)(1 - z) * BDIM * OUTDIM;
        const float sc = 1.0f / (float)INDIM;
#pragma unroll
        for (int mf = 0; mf < 2; ++mf) {
            int m = m0 + mbase + mf * 16 + l4;
            // fixed z-order rv sum => deterministic
            float rva0 = g_rvp[m] + g_rvp[BDIM + m];
            float rva1 = g_rvp[m + 8] + g_rvp[BDIM + m + 8];
#pragma unroll
            for (int nf = 0; nf < 4; ++nf) {
                int n = n0 + nbase + nf * 8 + l2;
                float2 p0 = *(const float2*)&src[(size_t)m * OUTDIM + n];
                float2 p1 = *(const float2*)&src[(size_t)(m + 8) * OUTDIM + n];
                *(float2*)&out[(size_t)m * OUTDIM + n] =
                    make_float2((acc[mf][nf][0] + p0.x + rva0) * sc,
                                (acc[mf][nf][1] + p0.y + rva0) * sc);
                *(float2*)&out[(size_t)(m + 8) * OUTDIM + n] =
                    make_float2((acc[mf][nf][2] + p1.x + rva1) * sc,
                                (acc[mf][nf][3] + p1.y + rva1) * sc);
            }
        }
        if (tid == 0)   // self-reset for next graph replay
            g_cnt[blockIdx.x * (OUTDIM / BN) + blockIdx.y] = 0;
    }
}

// ---------------------------------------------------------------------------
extern "C" void kernel_launch(void* const* d_in, const int* in_sizes, int n_in,
                              void* d_out, int out_size) {
    const float *x = nullptr, *coefs = nullptr, *aat = nullptr;
    const float *resid_scale = nullptr, *spline_scale = nullptr;
    for (int i = 0; i < n_in; i++) {
        switch (in_sizes[i]) {
            case BDIM * INDIM:        x            = (const float*)d_in[i]; break;
            case INDIM * OUTDIM * NC: coefs        = (const float*)d_in[i]; break;
            case 1:                   aat          = (const float*)d_in[i]; break;
            case INDIM:               resid_scale  = (const float*)d_in[i]; break;
            case INDIM * OUTDIM:      spline_scale = (const float*)d_in[i]; break;
            default: break;
        }
    }
    float* out = (float*)d_out;

    cudaFuncSetAttribute(gemm_fused, cudaFuncAttributeMaxDynamicSharedMemorySize, GEMM_SMEM);

    build_W_kernel<<<(INDIM * OUTDIM * NC / 4) / 256, 256>>>(coefs, spline_scale);
    dim3 grid(BDIM / BM, OUTDIM / BN, KSPLIT);
    gemm_fused<<<grid, 128, GEMM_SMEM>>>(out, x, resid_scale, aat);
}

// round 9
// speedup vs baseline: 1.3052x; 1.3052x over previous
#include <cuda_runtime.h>
#include <cuda_bf16.h>
#include <cstdint>
#include <math.h>

#define BDIM   4096
#define INDIM  256
#define OUTDIM 256
#define NC     8
#define KDIM   (INDIM * NC)      // 2048
#define KSPLIT 2
#define KHALF  (KDIM / KSPLIT)   // 1024

// ---------------- scratch (static device globals; no allocations) ----------
__device__ __nv_bfloat16 g_Bh[(size_t)OUTDIM * KDIM];      // 1 MB  B, [o][k]
__device__ float g_part[(size_t)KSPLIT * BDIM * OUTDIM];   // 8 MB  partials
__device__ float g_rvp[KSPLIT * BDIM];                     // rv partials

// ---------------------------------------------------------------------------
// 1) B = W^T:  g_Bh[o][i*8+c] = bf16( spline_scale[i,o] * coefs[i,o,c] )
//    (exact R6 version)
// ---------------------------------------------------------------------------
__global__ __launch_bounds__(256) void build_W_kernel(
    const float* __restrict__ coefs, const float* __restrict__ spline_scale) {
    int idx = blockIdx.x * 256 + threadIdx.x;  // i*256 + o
    int i = idx >> 8, o = idx & 255;
    float ss = spline_scale[idx];
    const float* cf = coefs + (size_t)idx * NC;
    uint4 uh;
    uint32_t* ph = (uint32_t*)&uh;
#pragma unroll
    for (int c = 0; c < 4; c++) {
        __nv_bfloat162 t = __floats2bfloat162_rn(ss * cf[2 * c], ss * cf[2 * c + 1]);
        ph[c] = *(uint32_t*)&t;
    }
    *(uint4*)&g_Bh[(size_t)o * KDIM + i * NC] = uh;
}

// ---------------------------------------------------------------------------
// 2) fused GEMM, single-pass bf16, split-K=2
//    CTA 64x64, BK=64, 128 threads (4 warps, warp tile 32x32)
//    A-build interleaved INTO the MMA phase (the one change vs R6)
// ---------------------------------------------------------------------------
#define BM 64
#define BN 64
#define BK 64
#define NTS (KHALF / BK)        // 16 k-chunks per split

#define ROWB 144                // 128B data + 16B pad
#define TILE_B (64 * ROWB)      // 9216 per tile
// stage layout: A @0, B @TILE_B
#define STAGE_B (2 * TILE_B)    // 18432
#define GEMM_SMEM (2 * STAGE_B) // 36864

__device__ __forceinline__ uint32_t smem_u32(const void* p) {
    uint32_t a;
    asm("{ .reg .u64 t; cvta.to.shared.u64 t, %1; cvt.u32.u64 %0, t; }"
        : "=r"(a) : "l"(p));
    return a;
}
__device__ __forceinline__ void cp16(uint32_t s, const void* g) {
    asm volatile("cp.async.cg.shared.global [%0], [%1], 16;" :: "r"(s), "l"(g));
}
__device__ __forceinline__ void ldsm_x4(uint32_t* r, uint32_t addr) {
    asm volatile("ldmatrix.sync.aligned.m8n8.x4.shared.b16 {%0,%1,%2,%3}, [%4];"
                 : "=r"(r[0]), "=r"(r[1]), "=r"(r[2]), "=r"(r[3]) : "r"(addr));
}
__device__ __forceinline__ void mma_bf16(float* d, const uint32_t* a, const uint32_t* b) {
    asm volatile(
        "mma.sync.aligned.m16n8k16.row.col.f32.bf16.bf16.f32 "
        "{%0,%1,%2,%3}, {%4,%5,%6,%7}, {%8,%9}, {%0,%1,%2,%3};"
        : "+f"(d[0]), "+f"(d[1]), "+f"(d[2]), "+f"(d[3])
        : "r"(a[0]), "r"(a[1]), "r"(a[2]), "r"(a[3]), "r"(b[0]), "r"(b[1]));
}

// B prefetch: 64 rows x 128B -> 512 x 16B chunks / 128 threads (R6 version)
__device__ __forceinline__ void prefetch_B(uint32_t sbase, int k0, int n0, int tid) {
#pragma unroll
    for (int p = 0; p < 4; ++p) {
        int idx = p * 128 + tid;           // 0..511
        int r = idx >> 3, c = idx & 7;
        cp16(sbase + TILE_B + r * ROWB + c * 16,
             g_Bh + (size_t)(n0 + r) * KDIM + k0 + c * 8);
    }
    asm volatile("cp.async.commit_group;" ::: "memory");
}

// A math+store from preloaded x values
__device__ __forceinline__ void a_math_store(
    char* abase, const float* xv, float rs, float* rv_acc,
    float alpha, const float* r1, const float* r2, int tid) {
#pragma unroll
    for (int p = 0; p < 4; ++p) {
        int b = p * 16 + (tid >> 3);
        float t = tanhf(xv[p]);
        rv_acc[p] += rs * t;

        float pr[NC];
        pr[0] = 1.0f;
        pr[1] = (alpha + 1.0f) + (alpha + alpha + 2.0f) * (t - 1.0f) * 0.5f;
#pragma unroll
        for (int n = 2; n < NC; n++)
            pr[n] = r1[n] * t * pr[n - 1] - r2[n] * pr[n - 2];

        uint4 uh;
        uint32_t* ph = (uint32_t*)&uh;
#pragma unroll
        for (int c = 0; c < 4; c++) {
            __nv_bfloat162 t2 = __floats2bfloat162_rn(pr[2 * c], pr[2 * c + 1]);
            ph[c] = *(uint32_t*)&t2;
        }
        *(uint4*)(abase + b * ROWB + (tid & 7) * 16) = uh;
    }
}

__global__ __launch_bounds__(128, 5) void gemm_fused(
    const float* __restrict__ x, const float* __restrict__ resid_scale,
    const float* __restrict__ aat) {
    extern __shared__ char smem[];
    const int tid  = threadIdx.x;
    const int wid  = tid >> 5;
    const int lane = tid & 31;
    const int m0   = blockIdx.x * BM;
    const int n0   = blockIdx.y * BN;
    const int z    = blockIdx.z;
    const int mbase = (wid & 1) * 32;
    const int nbase = (wid >> 1) * 32;
    const uint32_t sb = smem_u32(smem);

    // recurrence coefficients computed locally
    const float alpha = tanhf(__ldg(aat));
    float r1[NC], r2[NC];
#pragma unroll
    for (int n = 2; n < NC; n++) {
        float c = 2.0f * n + 2.0f * alpha;
        float A = 2.0f * n * (n + 2.0f * alpha) * (c - 2.0f);
        r1[n] = (c - 1.0f) * c * (c - 2.0f) / A;
        r2[n] = 2.0f * (n + alpha - 1.0f) * (n + alpha - 1.0f) * c / A;
    }

    float acc[2][4][4];
#pragma unroll
    for (int i = 0; i < 2; i++)
#pragma unroll
        for (int j = 0; j < 4; j++)
#pragma unroll
            for (int r = 0; r < 4; r++) acc[i][j][r] = 0.0f;
    float rv_acc[4] = {0.f, 0.f, 0.f, 0.f};

    // ldmatrix per-lane address pieces (mapping verified R3-R6)
    const int g  = lane >> 3;
    const int lr = lane & 7;
    const int a_row_off = lr + ((g & 1) ? 8 : 0);
    const int kb_off    = (g >= 2) ? 16 : 0;

    const int ibase = z * (KHALF / NC);   // i-range of this split
    const int il    = tid & 7;
    const int brow  = tid >> 3;

    // prologue: A(0) into stage0, B(0), B(1)
    float xv[4], rs;
    {
        int i = ibase + il;
        rs = resid_scale[i];
#pragma unroll
        for (int p = 0; p < 4; ++p)
            xv[p] = x[(size_t)(m0 + p * 16 + brow) * INDIM + i];
    }
    a_math_store(smem, xv, rs, rv_acc, alpha, r1, r2, tid);
    prefetch_B(sb, z * KHALF, n0, tid);
    prefetch_B(sb + STAGE_B, z * KHALF + BK, n0, tid);
    asm volatile("cp.async.wait_group 1;" ::: "memory");
    __syncthreads();

    for (int kt = 0; kt < NTS; ++kt) {
        const int s = kt & 1;
        const uint32_t st = sb + s * STAGE_B;
        const bool more = (kt + 1 < NTS);

        // x loads for stage kt+1 issued BEFORE the MMA phase (latency hides)
        if (more) {
            int i = ibase + (kt + 1) * 8 + il;
            rs = resid_scale[i];
#pragma unroll
            for (int p = 0; p < 4; ++p)
                xv[p] = x[(size_t)(m0 + p * 16 + brow) * INDIM + i];
        }

        // ---- MMA phase on stage s ----
#pragma unroll
        for (int ks = 0; ks < 4; ++ks) {
            uint32_t a[2][4], b[4][2];
#pragma unroll
            for (int mf = 0; mf < 2; ++mf) {
                uint32_t row = mbase + mf * 16 + a_row_off;
                ldsm_x4(a[mf], st + row * ROWB + ks * 32 + kb_off);
            }
#pragma unroll
            for (int np = 0; np < 2; ++np) {
                uint32_t row = nbase + np * 16 + lr + ((g >= 2) ? 8 : 0);
                uint32_t kb2 = ks * 32 + ((g & 1) ? 16 : 0);
                uint32_t r4[4];
                ldsm_x4(r4, st + TILE_B + row * ROWB + kb2);
                b[2 * np][0] = r4[0];     b[2 * np][1] = r4[1];
                b[2 * np + 1][0] = r4[2]; b[2 * np + 1][1] = r4[3];
            }
#pragma unroll
            for (int mf = 0; mf < 2; ++mf)
#pragma unroll
                for (int nf = 0; nf < 4; ++nf)
                    mma_bf16(acc[mf][nf], a[mf], b[nf]);
        }

        // ---- A(kt+1) math+store into stage s^1, overlapping the MMAs above
        // (s^1's A-region was last read at kt-1; everyone passed that barrier)
        if (more)
            a_math_store(smem + (s ^ 1) * STAGE_B, xv, rs, rv_acc,
                         alpha, r1, r2, tid);

        __syncthreads();   // all warps done reading stage s; A(kt+1) visible

        if (more) {
            if (kt + 2 < NTS) {
                prefetch_B(st, z * KHALF + (kt + 2) * BK, n0, tid);
                asm volatile("cp.async.wait_group 1;" ::: "memory");
            } else {
                asm volatile("cp.async.wait_group 0;" ::: "memory");
            }
            __syncthreads();   // B(kt+1) arrived and visible
        }
    }

    // rv partial: reduce 8 lanes (same b); all warps store disjoint slots
    if (blockIdx.y == 0) {
#pragma unroll
        for (int p = 0; p < 4; ++p) {
            float v = rv_acc[p];
            v += __shfl_xor_sync(0xffffffffu, v, 1);
            v += __shfl_xor_sync(0xffffffffu, v, 2);
            v += __shfl_xor_sync(0xffffffffu, v, 4);
            if ((lane & 7) == 0)
                g_rvp[z * BDIM + m0 + p * 16 + brow] = v;
        }
    }

    // write partial tile
    float* dst = g_part + (size_t)z * BDIM * OUTDIM;
    const int l4 = lane >> 2, l2 = (lane & 3) * 2;
#pragma unroll
    for (int mf = 0; mf < 2; ++mf) {
        int m = m0 + mbase + mf * 16 + l4;
#pragma unroll
        for (int nf = 0; nf < 4; ++nf) {
            int n = n0 + nbase + nf * 8 + l2;
            *(float2*)&dst[(size_t)m * OUTDIM + n] =
                make_float2(acc[mf][nf][0], acc[mf][nf][1]);
            *(float2*)&dst[(size_t)(m + 8) * OUTDIM + n] =
                make_float2(acc[mf][nf][2], acc[mf][nf][3]);
        }
    }
}

// ---------------------------------------------------------------------------
// 3) combine: out = (part0 + part1 + rv0 + rv1) / IN
// ---------------------------------------------------------------------------
__global__ __launch_bounds__(256) void combine_kernel(float* __restrict__ out) {
    int idx = blockIdx.x * 256 + threadIdx.x;   // float4 index
    int m = idx >> 6, c4 = (idx & 63) * 4;
    size_t o0 = (size_t)m * OUTDIM + c4;
    float4 a = *(float4*)&g_part[o0];
    float4 b = *(float4*)&g_part[(size_t)BDIM * OUTDIM + o0];
    float rv = g_rvp[m] + g_rvp[BDIM + m];
    const float s = 1.0f / (float)INDIM;
    float4 o;
    o.x = (a.x + b.x + rv) * s;
    o.y = (a.y + b.y + rv) * s;
    o.z = (a.z + b.z + rv) * s;
    o.w = (a.w + b.w + rv) * s;
    *(float4*)&out[o0] = o;
}

// ---------------------------------------------------------------------------
extern "C" void kernel_launch(void* const* d_in, const int* in_sizes, int n_in,
                              void* d_out, int out_size) {
    const float *x = nullptr, *coefs = nullptr, *aat = nullptr;
    const float *resid_scale = nullptr, *spline_scale = nullptr;
    for (int i = 0; i < n_in; i++) {
        switch (in_sizes[i]) {
            case BDIM * INDIM:        x            = (const float*)d_in[i]; break;
            case INDIM * OUTDIM * NC: coefs        = (const float*)d_in[i]; break;
            case 1:                   aat          = (const float*)d_in[i]; break;
            case INDIM:               resid_scale  = (const float*)d_in[i]; break;
            case INDIM * OUTDIM:      spline_scale = (const float*)d_in[i]; break;
            default: break;
        }
    }
    float* out = (float*)d_out;

    cudaFuncSetAttribute(gemm_fused, cudaFuncAttributeMaxDynamicSharedMemorySize, GEMM_SMEM);

    build_W_kernel<<<(INDIM * OUTDIM) / 256, 256>>>(coefs, spline_scale);
    dim3 grid(BDIM / BM, OUTDIM / BN, KSPLIT);
    gemm_fused<<<grid, 128, GEMM_SMEM>>>(x, resid_scale, aat);
    combine_kernel<<<(BDIM * OUTDIM / 4) / 256, 256>>>(out);
}

// round 10
// speedup vs baseline: 1.3281x; 1.0176x over previous
#include <cuda_runtime.h>
#include <cuda_bf16.h>
#include <cstdint>
#include <math.h>

#define BDIM   4096
#define INDIM  256
#define OUTDIM 256
#define NC     8
#define KDIM   (INDIM * NC)      // 2048
#define KSPLIT 2
#define KHALF  (KDIM / KSPLIT)   // 1024

// ---------------- scratch (static device globals; no allocations) ----------
__device__ __nv_bfloat16 g_Bh[(size_t)OUTDIM * KDIM];      // 1 MB  B, [o][k]
__device__ float g_part[(size_t)KSPLIT * BDIM * OUTDIM];   // 8 MB  partials
__device__ float g_rvp[KSPLIT * BDIM];                     // rv partials

// ---------------------------------------------------------------------------
// 1) B = W^T:  g_Bh[o][i*8+c] = bf16( spline_scale[i,o] * coefs[i,o,c] )
// ---------------------------------------------------------------------------
__global__ __launch_bounds__(256) void build_W_kernel(
    const float* __restrict__ coefs, const float* __restrict__ spline_scale) {
    int idx = blockIdx.x * 256 + threadIdx.x;  // i*256 + o
    int i = idx >> 8, o = idx & 255;
    float ss = spline_scale[idx];
    const float* cf = coefs + (size_t)idx * NC;
    uint4 uh;
    uint32_t* ph = (uint32_t*)&uh;
#pragma unroll
    for (int c = 0; c < 4; c++) {
        __nv_bfloat162 t = __floats2bfloat162_rn(ss * cf[2 * c], ss * cf[2 * c + 1]);
        ph[c] = *(uint32_t*)&t;
    }
    *(uint4*)&g_Bh[(size_t)o * KDIM + i * NC] = uh;
}

// ---------------------------------------------------------------------------
// 2) fused GEMM, single-pass bf16, split-K=2
//    CTA 64x64, BK=64, 128 threads (4 warps, warp tile 32x32)
//    A: 2-deep ring (computed in-kernel); B: 3-deep cp.async ring
//    => ONE __syncthreads per stage
// ---------------------------------------------------------------------------
#define BM 64
#define BN 64
#define BK 64
#define NTS (KHALF / BK)        // 16 k-chunks per split

#define ROWB 144                // 128B data + 16B pad
#define TILE_B (64 * ROWB)      // 9216 per tile
// layout: A0 @0, A1 @TILE_B, B0 @2*TILE_B, B1 @3*TILE_B, B2 @4*TILE_B
#define GEMM_SMEM (5 * TILE_B)  // 46080

__device__ __forceinline__ uint32_t smem_u32(const void* p) {
    uint32_t a;
    asm("{ .reg .u64 t; cvta.to.shared.u64 t, %1; cvt.u32.u64 %0, t; }"
        : "=r"(a) : "l"(p));
    return a;
}
__device__ __forceinline__ void cp16(uint32_t s, const void* g) {
    asm volatile("cp.async.cg.shared.global [%0], [%1], 16;" :: "r"(s), "l"(g));
}
__device__ __forceinline__ void ldsm_x4(uint32_t* r, uint32_t addr) {
    asm volatile("ldmatrix.sync.aligned.m8n8.x4.shared.b16 {%0,%1,%2,%3}, [%4];"
                 : "=r"(r[0]), "=r"(r[1]), "=r"(r[2]), "=r"(r[3]) : "r"(addr));
}
__device__ __forceinline__ void mma_bf16(float* d, const uint32_t* a, const uint32_t* b) {
    asm volatile(
        "mma.sync.aligned.m16n8k16.row.col.f32.bf16.bf16.f32 "
        "{%0,%1,%2,%3}, {%4,%5,%6,%7}, {%8,%9}, {%0,%1,%2,%3};"
        : "+f"(d[0]), "+f"(d[1]), "+f"(d[2]), "+f"(d[3])
        : "r"(a[0]), "r"(a[1]), "r"(a[2]), "r"(a[3]), "r"(b[0]), "r"(b[1]));
}

// B prefetch into a given B-slot base: 64 rows x 128B -> 512 x 16B chunks
__device__ __forceinline__ void prefetch_B(uint32_t dst, int k0, int n0, int tid) {
#pragma unroll
    for (int p = 0; p < 4; ++p) {
        int idx = p * 128 + tid;           // 0..511
        int r = idx >> 3, c = idx & 7;
        cp16(dst + r * ROWB + c * 16,
             g_Bh + (size_t)(n0 + r) * KDIM + k0 + c * 8);
    }
    asm volatile("cp.async.commit_group;" ::: "memory");
}

// A math+store from preloaded x values
__device__ __forceinline__ void a_math_store(
    char* abase, const float* xv, float rs, float* rv_acc,
    float alpha, const float* r1, const float* r2, int tid) {
#pragma unroll
    for (int p = 0; p < 4; ++p) {
        int b = p * 16 + (tid >> 3);
        float t = tanhf(xv[p]);
        rv_acc[p] += rs * t;

        float pr[NC];
        pr[0] = 1.0f;
        pr[1] = (alpha + 1.0f) + (alpha + alpha + 2.0f) * (t - 1.0f) * 0.5f;
#pragma unroll
        for (int n = 2; n < NC; n++)
            pr[n] = r1[n] * t * pr[n - 1] - r2[n] * pr[n - 2];

        uint4 uh;
        uint32_t* ph = (uint32_t*)&uh;
#pragma unroll
        for (int c = 0; c < 4; c++) {
            __nv_bfloat162 t2 = __floats2bfloat162_rn(pr[2 * c], pr[2 * c + 1]);
            ph[c] = *(uint32_t*)&t2;
        }
        *(uint4*)(abase + b * ROWB + (tid & 7) * 16) = uh;
    }
}

__global__ __launch_bounds__(128, 4) void gemm_fused(
    const float* __restrict__ x, const float* __restrict__ resid_scale,
    const float* __restrict__ aat) {
    extern __shared__ char smem[];
    const int tid  = threadIdx.x;
    const int wid  = tid >> 5;
    const int lane = tid & 31;
    const int m0   = blockIdx.x * BM;
    const int n0   = blockIdx.y * BN;
    const int z    = blockIdx.z;
    const int mbase = (wid & 1) * 32;
    const int nbase = (wid >> 1) * 32;
    const uint32_t sb = smem_u32(smem);

    // recurrence coefficients computed locally
    const float alpha = tanhf(__ldg(aat));
    float r1[NC], r2[NC];
#pragma unroll
    for (int n = 2; n < NC; n++) {
        float c = 2.0f * n + 2.0f * alpha;
        float A = 2.0f * n * (n + 2.0f * alpha) * (c - 2.0f);
        r1[n] = (c - 1.0f) * c * (c - 2.0f) / A;
        r2[n] = 2.0f * (n + alpha - 1.0f) * (n + alpha - 1.0f) * c / A;
    }

    float acc[2][4][4];
#pragma unroll
    for (int i = 0; i < 2; i++)
#pragma unroll
        for (int j = 0; j < 4; j++)
#pragma unroll
            for (int r = 0; r < 4; r++) acc[i][j][r] = 0.0f;
    float rv_acc[4] = {0.f, 0.f, 0.f, 0.f};

    // ldmatrix per-lane address pieces (mapping verified R3-R9)
    const int g  = lane >> 3;
    const int lr = lane & 7;
    const int a_row_off = lr + ((g & 1) ? 8 : 0);
    const int kb_off    = (g >= 2) ? 16 : 0;

    const int ibase = z * (KHALF / NC);   // i-range of this split
    const int il    = tid & 7;
    const int brow  = tid >> 3;

    // prologue: A(0) -> A0, B(0) -> Bslot0, B(1) -> Bslot1
    float xv[4], rs;
    {
        int i = ibase + il;
        rs = resid_scale[i];
#pragma unroll
        for (int p = 0; p < 4; ++p)
            xv[p] = x[(size_t)(m0 + p * 16 + brow) * INDIM + i];
    }
    a_math_store(smem, xv, rs, rv_acc, alpha, r1, r2, tid);
    prefetch_B(sb + 2 * TILE_B, z * KHALF, n0, tid);
    prefetch_B(sb + 3 * TILE_B, z * KHALF + BK, n0, tid);
    asm volatile("cp.async.wait_group 1;" ::: "memory");
    __syncthreads();

#pragma unroll 4
    for (int kt = 0; kt < NTS; ++kt) {
        const int sa = kt & 1;
        const int sb3 = kt % 3;
        const uint32_t stA = sb + sa * TILE_B;
        const uint32_t stB = sb + (2 + sb3) * TILE_B;
        const bool more = (kt + 1 < NTS);

        // x loads for stage kt+1 issued first (latency hides under MMAs)
        if (more) {
            int i = ibase + (kt + 1) * 8 + il;
            rs = resid_scale[i];
#pragma unroll
            for (int p = 0; p < 4; ++p)
                xv[p] = x[(size_t)(m0 + p * 16 + brow) * INDIM + i];
        }

        // ---- MMA phase: A[sa] x B[sb3] ----
#pragma unroll
        for (int ks = 0; ks < 4; ++ks) {
            uint32_t a[2][4], b[4][2];
#pragma unroll
            for (int mf = 0; mf < 2; ++mf) {
                uint32_t row = mbase + mf * 16 + a_row_off;
                ldsm_x4(a[mf], stA + row * ROWB + ks * 32 + kb_off);
            }
#pragma unroll
            for (int np = 0; np < 2; ++np) {
                uint32_t row = nbase + np * 16 + lr + ((g >= 2) ? 8 : 0);
                uint32_t kb2 = ks * 32 + ((g & 1) ? 16 : 0);
                uint32_t r4[4];
                ldsm_x4(r4, stB + row * ROWB + kb2);
                b[2 * np][0] = r4[0];     b[2 * np][1] = r4[1];
                b[2 * np + 1][0] = r4[2]; b[2 * np + 1][1] = r4[3];
            }
#pragma unroll
            for (int mf = 0; mf < 2; ++mf)
#pragma unroll
                for (int nf = 0; nf < 4; ++nf)
                    mma_bf16(acc[mf][nf], a[mf], b[nf]);
        }

        // ---- A(kt+1) into A[sa^1]: last read at kt-1, barrier passed ----
        if (more)
            a_math_store(smem + (sa ^ 1) * TILE_B, xv, rs, rv_acc,
                         alpha, r1, r2, tid);

        // ---- B(kt+2) into Bslot[(kt+2)%3]: last read at kt-1, safe ----
        if (kt + 2 < NTS) {
            prefetch_B(sb + (2 + (kt + 2) % 3) * TILE_B,
                       z * KHALF + (kt + 2) * BK, n0, tid);
            asm volatile("cp.async.wait_group 1;" ::: "memory");  // B(kt+1) done
        } else if (more) {
            asm volatile("cp.async.wait_group 0;" ::: "memory");
        }

        if (more) __syncthreads();   // single barrier per stage
    }

    // rv partial: reduce 8 lanes (same b); all warps store disjoint slots
    if (blockIdx.y == 0) {
#pragma unroll
        for (int p = 0; p < 4; ++p) {
            float v = rv_acc[p];
            v += __shfl_xor_sync(0xffffffffu, v, 1);
            v += __shfl_xor_sync(0xffffffffu, v, 2);
            v += __shfl_xor_sync(0xffffffffu, v, 4);
            if ((lane & 7) == 0)
                g_rvp[z * BDIM + m0 + p * 16 + brow] = v;
        }
    }

    // write partial tile
    float* dst = g_part + (size_t)z * BDIM * OUTDIM;
    const int l4 = lane >> 2, l2 = (lane & 3) * 2;
#pragma unroll
    for (int mf = 0; mf < 2; ++mf) {
        int m = m0 + mbase + mf * 16 + l4;
#pragma unroll
        for (int nf = 0; nf < 4; ++nf) {
            int n = n0 + nbase + nf * 8 + l2;
            *(float2*)&dst[(size_t)m * OUTDIM + n] =
                make_float2(acc[mf][nf][0], acc[mf][nf][1]);
            *(float2*)&dst[(size_t)(m + 8) * OUTDIM + n] =
                make_float2(acc[mf][nf][2], acc[mf][nf][3]);
        }
    }
}

// ---------------------------------------------------------------------------
// 3) combine: out = (part0 + part1 + rv0 + rv1) / IN
// ---------------------------------------------------------------------------
__global__ __launch_bounds__(256) void combine_kernel(float* __restrict__ out) {
    int idx = blockIdx.x * 256 + threadIdx.x;   // float4 index
    int m = idx >> 6, c4 = (idx & 63) * 4;
    size_t o0 = (size_t)m * OUTDIM + c4;
    float4 a = *(float4*)&g_part[o0];
    float4 b = *(float4*)&g_part[(size_t)BDIM * OUTDIM + o0];
    float rv = g_rvp[m] + g_rvp[BDIM + m];
    const float s = 1.0f / (float)INDIM;
    float4 o;
    o.x = (a.x + b.x + rv) * s;
    o.y = (a.y + b.y + rv) * s;
    o.z = (a.z + b.z + rv) * s;
    o.w = (a.w + b.w + rv) * s;
    *(float4*)&out[o0] = o;
}

// ---------------------------------------------------------------------------
extern "C" void kernel_launch(void* const* d_in, const int* in_sizes, int n_in,
                              void* d_out, int out_size) {
    const float *x = nullptr, *coefs = nullptr, *aat = nullptr;
    const float *resid_scale = nullptr, *spline_scale = nullptr;
    for (int i = 0; i < n_in; i++) {
        switch (in_sizes[i]) {
            case BDIM * INDIM:        x            = (const float*)d_in[i]; break;
            case INDIM * OUTDIM * NC: coefs        = (const float*)d_in[i]; break;
            case 1:                   aat          = (const float*)d_in[i]; break;
            case INDIM:               resid_scale  = (const float*)d_in[i]; break;
            case INDIM * OUTDIM:      spline_scale = (const float*)d_in[i]; break;
            default: break;
        }
    }
    float* out = (float*)d_out;

    cudaFuncSetAttribute(gemm_fused, cudaFuncAttributeMaxDynamicSharedMemorySize, GEMM_SMEM);

    build_W_kernel<<<(INDIM * OUTDIM) / 256, 256>>>(coefs, spline_scale);
    dim3 grid(BDIM / BM, OUTDIM / BN, KSPLIT);
    gemm_fused<<<grid, 128, GEMM_SMEM>>>(x, resid_scale, aat);
    combine_kernel<<<(BDIM * OUTDIM / 4) / 256, 256>>>(out);
}